// round 8
// baseline (speedup 1.0000x reference)
#include <cuda_runtime.h>
#include <math.h>

#define NLEAF 128
#define BT 64          // threads per block; each thread handles TWO batch elements

// ---------------------------------------------------------------------------
// Compile-time replication of numpy RandomState(0).permutation(128) x 3
// ---------------------------------------------------------------------------
struct PermTable { int p[3][NLEAF]; };

static constexpr unsigned int mt_next(unsigned int* mt, int& pos) {
    if (pos >= 624) {
        for (int i = 0; i < 624; i++) {
            unsigned int y = (mt[i] & 0x80000000u) | (mt[(i + 1) % 624] & 0x7fffffffu);
            unsigned int v = mt[(i + 397) % 624] ^ (y >> 1);
            if (y & 1u) v ^= 0x9908b0dfu;
            mt[i] = v;
        }
        pos = 0;
    }
    unsigned int y = mt[pos++];
    y ^= y >> 11;
    y ^= (y << 7) & 0x9d2c5680u;
    y ^= (y << 15) & 0xefc60000u;
    y ^= y >> 18;
    return y;
}

static constexpr unsigned int rk_interval(unsigned int mx, unsigned int* mt, int& pos) {
    if (mx == 0u) return 0u;
    unsigned int mask = mx;
    mask |= mask >> 1; mask |= mask >> 2; mask |= mask >> 4;
    mask |= mask >> 8; mask |= mask >> 16;
    while (true) {
        unsigned int value = mt_next(mt, pos) & mask;
        if (value <= mx) return value;
    }
}

static constexpr PermTable make_perms() {
    unsigned int mt[624] = {};
    unsigned int s = 0u;
    for (int i = 0; i < 624; i++) {
        mt[i] = s;
        s = 1812433253u * (s ^ (s >> 30)) + (unsigned int)i + 1u;
    }
    int pos = 624;
    PermTable t{};
    for (int k = 0; k < 3; k++) {
        int arr[NLEAF] = {};
        for (int i = 0; i < NLEAF; i++) arr[i] = i;
        for (int i = NLEAF - 1; i >= 1; i--) {
            unsigned int j = rk_interval((unsigned int)i, mt, pos);
            int tmp = arr[i]; arr[i] = arr[(int)j]; arr[(int)j] = tmp;
        }
        for (int i = 0; i < NLEAF; i++) t.p[k][i] = arr[i];
    }
    return t;
}

// ---------------------------------------------------------------------------
// Compile-time greedy leaf schedule minimizing simultaneously-open product
// groups across all 3 permutations, with register-slot allocation.
// ---------------------------------------------------------------------------
struct Sched {
    int leaf[NLEAF];
    int slot[NLEAF][3];
    unsigned char first[NLEAF];
    unsigned char last[NLEAF];
    int maxslots;
};

static constexpr Sched make_sched() {
    PermTable p = make_perms();
    int grp[3][NLEAF] = {};
    for (int o = 0; o < 3; o++)
        for (int i = 0; i < NLEAF; i++)
            grp[o][p.p[o][i]] = o * 32 + i / 4;

    int  cnt[96]   = {};
    int  gslot[96] = {};
    for (int g = 0; g < 96; g++) gslot[g] = -1;
    bool used[NLEAF] = {};
    bool slotfree[NLEAF] = {};
    for (int s2 = 0; s2 < NLEAF; s2++) slotfree[s2] = true;

    Sched sc{};
    int maxslot = 0;

    for (int step = 0; step < NLEAF; step++) {
        int best = -1, bestdelta = 99, besttie = -1;
        for (int j = 0; j < NLEAF; j++) {
            if (used[j]) continue;
            int delta = 0, tie = 0;
            for (int o = 0; o < 3; o++) {
                int g = grp[o][j];
                if (cnt[g] == 0) delta++;
                if (cnt[g] == 3) delta--;
                tie += cnt[g];
            }
            if (delta < bestdelta || (delta == bestdelta && tie > besttie)) {
                best = j; bestdelta = delta; besttie = tie;
            }
        }
        used[best] = true;
        sc.leaf[step] = best;
        sc.first[step] = 0; sc.last[step] = 0;
        for (int o = 0; o < 3; o++) {
            int g = grp[o][best];
            if (cnt[g] == 0) {
                int s2 = 0;
                while (!slotfree[s2]) s2++;
                slotfree[s2] = false;
                gslot[g] = s2;
                sc.first[step] = (unsigned char)(sc.first[step] | (1 << o));
                if (s2 + 1 > maxslot) maxslot = s2 + 1;
            }
            sc.slot[step][o] = gslot[g];
            cnt[g]++;
            if (cnt[g] == 4)
                sc.last[step] = (unsigned char)(sc.last[step] | (1 << o));
        }
        for (int o = 0; o < 3; o++) {
            int g = grp[o][best];
            if (cnt[g] == 4 && gslot[g] >= 0) {
                slotfree[gslot[g]] = true;
                gslot[g] = -1;
            }
        }
    }
    sc.maxslots = maxslot;
    return sc;
}

static constexpr Sched SCHED = make_sched();

// ---------------------------------------------------------------------------
// Device globals
//   g_m0 = {aA, aB, Df, Ef}   (fermi tau coefs; dk factor for fermi; Ef shared)
//   g_m1 = {B0*KF, B1, B2, B3}
//   g_m2 = {C, Db, PA, PB}    (C==0 marks a FERMI leaf; bose C>0 always)
// ---------------------------------------------------------------------------
__device__ float4 g_m0[NLEAF];
__device__ float4 g_m1[NLEAF];
__device__ float4 g_m2[NLEAF];
__device__ float  g_c [8];

__global__ void prep_kernel(const int* __restrict__ lftype,
                            const int* __restrict__ lforders,
                            const int* __restrict__ taui,
                            const int* __restrict__ tauo,
                            const int* __restrict__ momIdx,
                            const float* __restrict__ lb,
                            const float* __restrict__ lv0)
{
    int j = threadIdx.x;
    const double PI_D   = 3.14159265358979323846264338327950288;
    const double LOG2E  = 1.44269504088896340735992468100189214;
    double KF_d = cbrt(9.0 * PI_D / 4.0) * 0.5;
    if (j == 0) {
        double EF   = KF_d * KF_d;
        double BETA = 10.0 / EF;
        double MAXK = 10.0 * KF_d;
        double t    = MAXK * 2.0 * PI_D * PI_D;
        double SC   = (t * t * t) * BETA * BETA / pow(2.0 * PI_D, 9.0);
        g_c[0] = (float)(BETA * LOG2E);     // BETA pre-scaled to log2 units
        g_c[1] = (float)(0.99177533 * EF);  // MU
        g_c[2] = (float)MAXK;
        g_c[3] = (float)SC;
        g_c[4] = (float)(PI_D / BETA);
    }
    int lt  = lftype[j];
    int lo1 = lforders[NLEAF + j];
    int dk  = (lforders[2 * NLEAF + j] == 1) ? 1 : 0;
    int ti  = taui[j];
    int to  = tauo[j];
    int m   = momIdx[j];

    bool fermi = (lt == 1);

    float B0  = lb[m];
    float B0K = (float)(KF_d) * B0;

    float aA = fermi ? (float)((to == 1) - (ti == 1)) : 0.0f;
    float aB = fermi ? (float)((to == 2) - (ti == 2)) : 0.0f;
    float Df = (fermi && dk) ? 2.0f * B0 : 0.0f;
    float Ef = dk ? 0.0f : 1.0f;

    float C  = fermi ? 0.0f : (float)(8.0 * PI_D * pow(0.5, (double)lo1));
    float Db = (!fermi && dk) ? (-2.0f * (float)(lo1 + 1)) * B0 : 0.0f;
    float PA = (lo1 >= 1) ? 1.0f : 0.0f;
    float PB = (lo1 >= 2) ? 1.0f : 0.0f;

    g_m0[j] = make_float4(aA, aB, Df, Ef);
    g_m1[j] = make_float4(B0K, lb[NLEAF + m], lb[2 * NLEAF + m], lb[3 * NLEAF + m]);
    g_m2[j] = make_float4(C, Db, PA, PB);
}

// ---------------------------------------------------------------------------
static __device__ __forceinline__ float ex2f(float x) {
    float r;
    asm("ex2.approx.ftz.f32 %0, %1;" : "=f"(r) : "f"(x));
    return r;
}
static __device__ __forceinline__ float rcpf(float x) {
    float r;
    asm("rcp.approx.ftz.f32 %0, %1;" : "=f"(r) : "f"(x));
    return r;
}

struct TS {
    float px[3], py[3], pz[3];
    float tA, tB;      // tau candidates pre-scaled by BETA*log2e
};

// Branchless single-element propagator given k2/kq0 and per-leaf constants.
static __device__ __forceinline__ float prop_one(float k2, float kq0,
                                                 float tA, float tB,
                                                 float MUc, float BETA2,
                                                 float4 m0, float4 m2)
{
    float disp = k2 - MUc;
    float tau  = fmaf(m0.x, tA, m0.y * tB);         // (v_o-v_i)*BETA*log2e
    bool  tp   = tau  > 0.0f;
    bool  dp   = disp > 0.0f;

    // fermi exponent arguments (log2 units); both always <= 0 -> stable
    float f1   = tp ? BETA2 : 0.0f;
    float f2   = dp ? -BETA2 : 0.0f;
    float aa   = (f1 + f2) - tau;
    float arga = disp * aa;
    float argb = -fabsf(disp) * BETA2;              // == disp * (dp ? -B : B)

    float ea  = ex2f(arga);
    float eb  = ex2f(argb);
    float den = 1.0f + eb;                          // in (1, 2]

    bool  pf    = (m2.x == 0.0f);                   // fermi leaf?
    float rcpin = pf ? den : (k2 + 0.5f);           // MASS2 = 0.5
    float r     = rcpf(rcpin);                      // shared reciprocal

    // fermi value
    float sgn  = tp ? 1.0f : -1.0f;
    float mf   = fmaf(kq0, m0.z, m0.w);             // dk ? kq0*2B0 : 1
    float valf = (ea * r) * (sgn * mf);

    // bose value: C * r^(lo1+1) * (dk ? kq0*r*Db : 1)
    float rm1 = r - 1.0f;
    float fb1 = fmaf(m2.z, rm1, 1.0f);              // PA ? r : 1
    float fb2 = fmaf(m2.w, rm1, 1.0f);              // PB ? r : 1
    float pw  = (r * fb1) * fb2;
    float mb  = fmaf(kq0 * r, m2.y, m0.w);          // dk ? kq0*r*Db : 1
    float valb = (m2.x * pw) * mb;

    return pf ? valf : valb;
}

// Evaluate leaf J for two independent batch elements sharing one metadata load.
template<int J>
static __device__ __forceinline__ void leaf_eval2(const TS& u, const TS& v,
                                                  float MUc, float BETA2,
                                                  const float4* __restrict__ sm0,
                                                  const float4* __restrict__ sm1,
                                                  const float4* __restrict__ sm2,
                                                  float& valU, float& valV)
{
    const float4 m0 = sm0[J];
    const float4 m1 = sm1[J];
    const float4 m2 = sm2[J];
    const float B1 = m1.y, B2 = m1.z, B3 = m1.w;

    float kq0U = fmaf(u.px[0], B1, fmaf(u.px[1], B2, fmaf(u.px[2], B3, m1.x)));
    float kq1U = fmaf(u.py[0], B1, fmaf(u.py[1], B2, u.py[2] * B3));
    float kq2U = fmaf(u.pz[0], B1, fmaf(u.pz[1], B2, u.pz[2] * B3));
    float k2U  = fmaf(kq0U, kq0U, fmaf(kq1U, kq1U, kq2U * kq2U));

    float kq0V = fmaf(v.px[0], B1, fmaf(v.px[1], B2, fmaf(v.px[2], B3, m1.x)));
    float kq1V = fmaf(v.py[0], B1, fmaf(v.py[1], B2, v.py[2] * B3));
    float kq2V = fmaf(v.pz[0], B1, fmaf(v.pz[1], B2, v.pz[2] * B3));
    float k2V  = fmaf(kq0V, kq0V, fmaf(kq1V, kq1V, kq2V * kq2V));

    valU = prop_one(k2U, kq0U, u.tA, u.tB, MUc, BETA2, m0, m2);
    valV = prop_one(k2V, kq0V, v.tA, v.tB, MUc, BETA2, m0, m2);
}

template<int STEP, int O>
static __device__ __forceinline__ void step_group(float (&pool)[NLEAF], float& acc, float val)
{
    constexpr int  S = SCHED.slot[STEP][O];
    constexpr bool F = (SCHED.first[STEP] >> O) & 1;
    constexpr bool L = (SCHED.last[STEP]  >> O) & 1;
    if constexpr (F) pool[S] = val; else pool[S] *= val;
    if constexpr (L) acc += pool[S];
}

template<int STEP> struct Walk {
    static __device__ __forceinline__ void run(const TS& u, const TS& v,
                                               float MUc, float BETA2,
                                               const float4* __restrict__ sm0,
                                               const float4* __restrict__ sm1,
                                               const float4* __restrict__ sm2,
                                               float (&poolU)[NLEAF], float (&poolV)[NLEAF],
                                               float (&aU)[3], float (&aV)[3])
    {
        constexpr int J = SCHED.leaf[STEP];
        float valU, valV;
        leaf_eval2<J>(u, v, MUc, BETA2, sm0, sm1, sm2, valU, valV);
        step_group<STEP, 0>(poolU, aU[0], valU);
        step_group<STEP, 1>(poolU, aU[1], valU);
        step_group<STEP, 2>(poolU, aU[2], valU);
        step_group<STEP, 0>(poolV, aV[0], valV);
        step_group<STEP, 1>(poolV, aV[1], valV);
        step_group<STEP, 2>(poolV, aV[2], valV);
        Walk<STEP + 1>::run(u, v, MUc, BETA2, sm0, sm1, sm2, poolU, poolV, aU, aV);
    }
};
template<> struct Walk<NLEAF> {
    static __device__ __forceinline__ void run(const TS&, const TS&, float, float,
                                               const float4*, const float4*, const float4*,
                                               float (&)[NLEAF], float (&)[NLEAF],
                                               float (&)[3], float (&)[3]) {}
};

// Load one element's variable row and build its TS + factor.
static __device__ __forceinline__ void load_elem(const float* __restrict__ var, int b,
                                                 float BETA2, float MAXKc,
                                                 TS& s, float& factor,
                                                 float& va0, float& va1)
{
    const float* p = var + (size_t)b * 11;
    va0 = __ldg(p + 0);
    va1 = __ldg(p + 1);
    s.tA = va0 * BETA2;
    s.tB = va1 * BETA2;
    factor = 1.0f;
    #pragma unroll
    for (int l = 0; l < 3; l++) {
        float pr = __ldg(p + 2 + l) * MAXKc;
        float th = __ldg(p + 5 + l) * 3.14159265358979f;
        float ph = __ldg(p + 8 + l) * 6.28318530717959f;
        float st, ct, sp, cp;
        __sincosf(th, &st, &ct);
        __sincosf(ph, &sp, &cp);
        float prst = pr * st;
        s.px[l] = prst * cp;
        s.py[l] = prst * sp;
        s.pz[l] = pr * ct;
        factor *= pr * pr * st;
    }
}

// ---------------------------------------------------------------------------
// Main kernel: 2 batch elements per thread, branchless leaf bodies forming
// one straight-line region so ptxas can interleave chains across steps.
// ---------------------------------------------------------------------------
__global__ __launch_bounds__(BT, 7) void feyn_kernel(const float* __restrict__ var,
                                                     float* __restrict__ out,
                                                     int half)
{
    __shared__ float4 sm0[NLEAF];
    __shared__ float4 sm1[NLEAF];
    __shared__ float4 sm2[NLEAF];

    const int tid = threadIdx.x;
    #pragma unroll
    for (int j = tid; j < NLEAF; j += BT) {
        sm0[j] = g_m0[j];
        sm1[j] = g_m1[j];
        sm2[j] = g_m2[j];
    }
    __syncthreads();

    const int b0 = blockIdx.x * BT + tid;
    if (b0 >= half) return;
    const int b1 = b0 + half;          // second element (always valid: batch even)

    const float BETA2  = g_c[0];
    const float MUc    = g_c[1];
    const float MAXKc  = g_c[2];
    const float SCALEc = g_c[3];
    const float PHC    = g_c[4];

    TS u, v;
    float facU, facV, va0U, va1U, va0V, va1V;
    load_elem(var, b0, BETA2, MAXKc, u, facU, va0U, va1U);
    load_elem(var, b1, BETA2, MAXKc, v, facV, va0V, va1V);

    float poolU[NLEAF], poolV[NLEAF];  // only SCHED.maxslots entries touched
    float aU[3] = {0.f, 0.f, 0.f};
    float aV[3] = {0.f, 0.f, 0.f};
    Walk<0>::run(u, v, MUc, BETA2, sm0, sm1, sm2, poolU, poolV, aU, aV);

    {
        float ph1 = __cosf(PHC * va0U);
        float ph2 = __cosf(PHC * va1U);
        out[b0] = SCALEc * facU * (aU[0] + aU[1] * ph1 + aU[2] * ph2);
    }
    {
        float ph1 = __cosf(PHC * va0V);
        float ph2 = __cosf(PHC * va1V);
        out[b1] = SCALEc * facV * (aV[0] + aV[1] * ph1 + aV[2] * ph2);
    }
}

// ---------------------------------------------------------------------------
extern "C" void kernel_launch(void* const* d_in, const int* in_sizes, int n_in,
                              void* d_out, int out_size)
{
    const float* var      = (const float*)d_in[0];
    const int*   lftype   = (const int*)d_in[2];
    const int*   lforders = (const int*)d_in[3];
    const int*   taui     = (const int*)d_in[4];
    const int*   tauo     = (const int*)d_in[5];
    const int*   momIdx   = (const int*)d_in[6];
    const float* lb       = (const float*)d_in[7];
    const float* lv0      = (const float*)d_in[8];

    const int batch = in_sizes[0] / 11;
    const int half  = batch / 2;

    prep_kernel<<<1, NLEAF>>>(lftype, lforders, taui, tauo, momIdx, lb, lv0);

    const int grid = (half + BT - 1) / BT;
    feyn_kernel<<<grid, BT>>>(var, (float*)d_out, half);
}

// round 10
// speedup vs baseline: 1.1323x; 1.1323x over previous
#include <cuda_runtime.h>
#include <math.h>

#define NLEAF 128
#define BT 64          // threads per block; ONE batch element per thread
#define POOL_SLOTS 48

// ---------------------------------------------------------------------------
// Compile-time replication of numpy RandomState(0).permutation(128) x 3
// ---------------------------------------------------------------------------
struct PermTable { int p[3][NLEAF]; };

static constexpr unsigned int mt_next(unsigned int* mt, int& pos) {
    if (pos >= 624) {
        for (int i = 0; i < 624; i++) {
            unsigned int y = (mt[i] & 0x80000000u) | (mt[(i + 1) % 624] & 0x7fffffffu);
            unsigned int v = mt[(i + 397) % 624] ^ (y >> 1);
            if (y & 1u) v ^= 0x9908b0dfu;
            mt[i] = v;
        }
        pos = 0;
    }
    unsigned int y = mt[pos++];
    y ^= y >> 11;
    y ^= (y << 7) & 0x9d2c5680u;
    y ^= (y << 15) & 0xefc60000u;
    y ^= y >> 18;
    return y;
}

static constexpr unsigned int rk_interval(unsigned int mx, unsigned int* mt, int& pos) {
    if (mx == 0u) return 0u;
    unsigned int mask = mx;
    mask |= mask >> 1; mask |= mask >> 2; mask |= mask >> 4;
    mask |= mask >> 8; mask |= mask >> 16;
    while (true) {
        unsigned int value = mt_next(mt, pos) & mask;
        if (value <= mx) return value;
    }
}

static constexpr PermTable make_perms() {
    unsigned int mt[624] = {};
    unsigned int s = 0u;
    for (int i = 0; i < 624; i++) {
        mt[i] = s;
        s = 1812433253u * (s ^ (s >> 30)) + (unsigned int)i + 1u;
    }
    int pos = 624;
    PermTable t{};
    for (int k = 0; k < 3; k++) {
        int arr[NLEAF] = {};
        for (int i = 0; i < NLEAF; i++) arr[i] = i;
        for (int i = NLEAF - 1; i >= 1; i--) {
            unsigned int j = rk_interval((unsigned int)i, mt, pos);
            int tmp = arr[i]; arr[i] = arr[(int)j]; arr[(int)j] = tmp;
        }
        for (int i = 0; i < NLEAF; i++) t.p[k][i] = arr[i];
    }
    return t;
}

// ---------------------------------------------------------------------------
// Compile-time greedy leaf schedule minimizing simultaneously-open product
// groups across all 3 permutations, with slot allocation.
// ---------------------------------------------------------------------------
struct Sched {
    int leaf[NLEAF];
    int slot[NLEAF][3];
    unsigned char first[NLEAF];   // bit o: step opens perm-o's group
    unsigned char last[NLEAF];    // bit o: step closes perm-o's group
    int maxslots;
};

static constexpr Sched make_sched() {
    PermTable p = make_perms();
    int grp[3][NLEAF] = {};
    for (int o = 0; o < 3; o++)
        for (int i = 0; i < NLEAF; i++)
            grp[o][p.p[o][i]] = o * 32 + i / 4;

    int  cnt[96]   = {};
    int  gslot[96] = {};
    for (int g = 0; g < 96; g++) gslot[g] = -1;
    bool used[NLEAF] = {};
    bool slotfree[NLEAF] = {};
    for (int s2 = 0; s2 < NLEAF; s2++) slotfree[s2] = true;

    Sched sc{};
    int maxslot = 0;

    for (int step = 0; step < NLEAF; step++) {
        int best = -1, bestdelta = 99, besttie = -1;
        for (int j = 0; j < NLEAF; j++) {
            if (used[j]) continue;
            int delta = 0, tie = 0;
            for (int o = 0; o < 3; o++) {
                int g = grp[o][j];
                if (cnt[g] == 0) delta++;
                if (cnt[g] == 3) delta--;
                tie += cnt[g];
            }
            if (delta < bestdelta || (delta == bestdelta && tie > besttie)) {
                best = j; bestdelta = delta; besttie = tie;
            }
        }
        used[best] = true;
        sc.leaf[step] = best;
        sc.first[step] = 0; sc.last[step] = 0;
        for (int o = 0; o < 3; o++) {
            int g = grp[o][best];
            if (cnt[g] == 0) {
                int s2 = 0;
                while (!slotfree[s2]) s2++;
                slotfree[s2] = false;
                gslot[g] = s2;
                sc.first[step] = (unsigned char)(sc.first[step] | (1 << o));
                if (s2 + 1 > maxslot) maxslot = s2 + 1;
            }
            sc.slot[step][o] = gslot[g];
            cnt[g]++;
            if (cnt[g] == 4)
                sc.last[step] = (unsigned char)(sc.last[step] | (1 << o));
        }
        for (int o = 0; o < 3; o++) {
            int g = grp[o][best];
            if (cnt[g] == 4 && gslot[g] >= 0) {
                slotfree[gslot[g]] = true;
                gslot[g] = -1;
            }
        }
    }
    sc.maxslots = maxslot;
    return sc;
}

static constexpr Sched SCHED = make_sched();
static_assert(SCHED.maxslots <= POOL_SLOTS, "slot pool overflow");

// Materialized copy for runtime indexing in device code.
__device__ const Sched d_sched = make_sched();

// ---------------------------------------------------------------------------
// Device globals (STEP-indexed, i.e. already in schedule order)
//   g_m0 = {ctrl_bits, u1, u2, u3}
//          fermi: u1=aA, u2=aB, u3=Df(=dk?2B0:0)
//          bose : u1=DbC(=dk? C*(-2(lo1+1))*B0 : 0), u2=EfC(=dk?0:C), u3=PA(lo1>=1)
//   g_m1 = {B0*KF, B1, B2, B3}
//   ctrl_bits: b0=fermi, b1=dk, b3=(lo1>=2),
//              slots (6b each): [4:10) [10:16) [16:22),
//              first: b22..24, last: b25..27
// ---------------------------------------------------------------------------
__device__ float4 g_m0[NLEAF];
__device__ float4 g_m1[NLEAF];
__device__ float  g_c [8];

__global__ void prep_kernel(const int* __restrict__ lftype,
                            const int* __restrict__ lforders,
                            const int* __restrict__ taui,
                            const int* __restrict__ tauo,
                            const int* __restrict__ momIdx,
                            const float* __restrict__ lb,
                            const float* __restrict__ lv0)
{
    int s = threadIdx.x;                  // step index
    const double PI_D   = 3.14159265358979323846264338327950288;
    const double LOG2E  = 1.44269504088896340735992468100189214;
    double KF_d = cbrt(9.0 * PI_D / 4.0) * 0.5;
    if (s == 0) {
        double EF   = KF_d * KF_d;
        double BETA = 10.0 / EF;
        double MAXK = 10.0 * KF_d;
        double t    = MAXK * 2.0 * PI_D * PI_D;
        double SC   = (t * t * t) * BETA * BETA / pow(2.0 * PI_D, 9.0);
        g_c[0] = (float)(BETA * LOG2E);     // BETA in log2 units
        g_c[1] = (float)(0.99177533 * EF);  // MU
        g_c[2] = (float)MAXK;
        g_c[3] = (float)SC;
        g_c[4] = (float)(PI_D / BETA);
    }
    int j   = d_sched.leaf[s];            // original leaf for this step
    int lt  = lftype[j];
    int lo1 = lforders[NLEAF + j];
    int dk  = (lforders[2 * NLEAF + j] == 1) ? 1 : 0;
    int ti  = taui[j];
    int to  = tauo[j];
    int m   = momIdx[j];

    bool fermi = (lt == 1);
    float B0  = lb[m];
    float B0K = (float)(KF_d) * B0;

    unsigned int bits = (fermi ? 1u : 0u)
                      | ((unsigned int)dk << 1)
                      | ((lo1 >= 2 ? 1u : 0u) << 3)
                      | ((unsigned int)d_sched.slot[s][0] << 4)
                      | ((unsigned int)d_sched.slot[s][1] << 10)
                      | ((unsigned int)d_sched.slot[s][2] << 16)
                      | ((unsigned int)d_sched.first[s] << 22)
                      | ((unsigned int)d_sched.last[s]  << 25);

    float u1, u2, u3;
    if (fermi) {
        u1 = (float)((to == 1) - (ti == 1));            // aA
        u2 = (float)((to == 2) - (ti == 2));            // aB
        u3 = dk ? 2.0f * B0 : 0.0f;                     // Df
    } else {
        double C = 8.0 * PI_D * pow(0.5, (double)lo1);
        u1 = dk ? (float)(C * (-2.0 * (double)(lo1 + 1))) * B0 : 0.0f;  // DbC
        u2 = dk ? 0.0f : (float)C;                      // EfC
        u3 = (lo1 >= 1) ? 1.0f : 0.0f;                  // PA
    }

    g_m0[s] = make_float4(__uint_as_float(bits), u1, u2, u3);
    g_m1[s] = make_float4(B0K, lb[NLEAF + m], lb[2 * NLEAF + m], lb[3 * NLEAF + m]);
}

// ---------------------------------------------------------------------------
static __device__ __forceinline__ float ex2f(float x) {
    float r;
    asm("ex2.approx.ftz.f32 %0, %1;" : "=f"(r) : "f"(x));
    return r;
}
static __device__ __forceinline__ float rcpf(float x) {
    float r;
    asm("rcp.approx.ftz.f32 %0, %1;" : "=f"(r) : "f"(x));
    return r;
}

// ---------------------------------------------------------------------------
// Main kernel: 1 element per thread, LOOPED over 128 steps (small I$ body),
// product-group pool in conflict-free shared memory.
// ---------------------------------------------------------------------------
__global__ __launch_bounds__(BT, 12) void feyn_kernel(const float* __restrict__ var,
                                                      float* __restrict__ out,
                                                      int batch)
{
    __shared__ float4 smA[NLEAF];
    __shared__ float4 smB[NLEAF];
    __shared__ float  pool[POOL_SLOTS * BT];

    const int tid = threadIdx.x;
    #pragma unroll
    for (int j = tid; j < NLEAF; j += BT) {
        smA[j] = g_m0[j];
        smB[j] = g_m1[j];
    }
    __syncthreads();

    const int b = blockIdx.x * BT + tid;
    if (b >= batch) return;

    const float BETA2  = g_c[0];
    const float MUc    = g_c[1];
    const float MAXKc  = g_c[2];
    const float SCALEc = g_c[3];
    const float PHC    = g_c[4];

    const float* p = var + (size_t)b * 11;
    const float va0 = __ldg(p + 0);
    const float va1 = __ldg(p + 1);
    const float tA = va0 * BETA2;
    const float tB = va1 * BETA2;

    float px[3], py[3], pz[3];
    float factor = 1.0f;
    #pragma unroll
    for (int l = 0; l < 3; l++) {
        float pr = __ldg(p + 2 + l) * MAXKc;
        float th = __ldg(p + 5 + l) * 3.14159265358979f;
        float ph = __ldg(p + 8 + l) * 6.28318530717959f;
        float st, ct, sp, cp;
        __sincosf(th, &st, &ct);
        __sincosf(ph, &sp, &cp);
        float prst = pr * st;
        px[l] = prst * cp;
        py[l] = prst * sp;
        pz[l] = pr * ct;
        factor *= pr * pr * st;
    }

    float* P = pool + tid;                 // this thread's pool column
    float a0 = 0.0f, a1 = 0.0f, a2 = 0.0f;

    #pragma unroll 4
    for (int s = 0; s < NLEAF; s++) {
        const float4 m0 = smA[s];
        const float4 m1 = smB[s];
        const unsigned int bits = __float_as_uint(m0.x);
        const float B1 = m1.y, B2 = m1.z, B3 = m1.w;

        float kq0 = fmaf(px[0], B1, fmaf(px[1], B2, fmaf(px[2], B3, m1.x)));
        float kq1 = fmaf(py[0], B1, fmaf(py[1], B2, py[2] * B3));
        float kq2 = fmaf(pz[0], B1, fmaf(pz[1], B2, pz[2] * B3));
        float k2  = fmaf(kq0, kq0, fmaf(kq1, kq1, kq2 * kq2));

        float val;
        if (bits & 1u) {
            // ---- fermi ----
            float disp = k2 - MUc;
            float tau  = fmaf(m0.y, tA, m0.z * tB);       // (v_o-v_i)*BETA*log2e
            bool  tp = tau  > 0.0f;
            bool  dp = disp > 0.0f;
            float f1 = tp ? BETA2 : 0.0f;
            float f2 = dp ? -BETA2 : 0.0f;
            float ea  = ex2f(disp * ((f1 + f2) - tau));    // arg <= 0
            float den = 1.0f + ex2f(-fabsf(disp) * BETA2); // den in (1,2]
            float r   = rcpf(den);
            float Ef  = (bits & 2u) ? 0.0f : 1.0f;
            float mf  = fmaf(kq0, m0.w, Ef);               // dk ? kq0*2B0 : 1
            mf = tp ? mf : -mf;
            val = (ea * r) * mf;
        } else {
            // ---- bose ----
            float r   = rcpf(k2 + 0.5f);                   // MASS2 = 0.5
            float rm1 = r - 1.0f;
            float t1  = fmaf(m0.w, rm1, 1.0f);             // PA ? r : 1
            float PB  = (bits & 8u) ? 1.0f : 0.0f;
            float t2  = fmaf(PB, rm1, 1.0f);               // PB ? r : 1
            float mb  = fmaf(kq0 * r, m0.y, m0.z);         // dk? kq0*r*DbC : EfC
            val = (r * t1) * (t2 * mb);
        }

        // ---- product-group updates (slots/flags from ctrl bits) ----
        {
            int  sl = (bits >> 4) & 63;
            float old = P[sl * BT];
            float c   = (bits & (1u << 22)) ? val : old * val;
            P[sl * BT] = c;
            if (bits & (1u << 25)) a0 += c;
        }
        {
            int  sl = (bits >> 10) & 63;
            float old = P[sl * BT];
            float c   = (bits & (1u << 23)) ? val : old * val;
            P[sl * BT] = c;
            if (bits & (1u << 26)) a1 += c;
        }
        {
            int  sl = (bits >> 16) & 63;
            float old = P[sl * BT];
            float c   = (bits & (1u << 24)) ? val : old * val;
            P[sl * BT] = c;
            if (bits & (1u << 27)) a2 += c;
        }
    }

    float ph1 = __cosf(PHC * va0);
    float ph2 = __cosf(PHC * va1);
    out[b] = SCALEc * factor * (a0 + a1 * ph1 + a2 * ph2);
}

// ---------------------------------------------------------------------------
extern "C" void kernel_launch(void* const* d_in, const int* in_sizes, int n_in,
                              void* d_out, int out_size)
{
    const float* var      = (const float*)d_in[0];
    const int*   lftype   = (const int*)d_in[2];
    const int*   lforders = (const int*)d_in[3];
    const int*   taui     = (const int*)d_in[4];
    const int*   tauo     = (const int*)d_in[5];
    const int*   momIdx   = (const int*)d_in[6];
    const float* lb       = (const float*)d_in[7];
    const float* lv0      = (const float*)d_in[8];

    const int batch = in_sizes[0] / 11;

    prep_kernel<<<1, NLEAF>>>(lftype, lforders, taui, tauo, momIdx, lb, lv0);

    const int grid = (batch + BT - 1) / BT;
    feyn_kernel<<<grid, BT>>>(var, (float*)d_out, batch);
}

// round 11
// speedup vs baseline: 1.3502x; 1.1925x over previous
#include <cuda_runtime.h>
#include <math.h>

#define NLEAF 128
#define BT 64          // threads per block; each thread handles TWO batch elements
#define POOL_SLOTS 48
#define POOL_E1_OFF (POOL_SLOTS * BT * 4)   // byte offset of element-1 pool

// ---------------------------------------------------------------------------
// Compile-time replication of numpy RandomState(0).permutation(128) x 3
// ---------------------------------------------------------------------------
struct PermTable { int p[3][NLEAF]; };

static constexpr unsigned int mt_next(unsigned int* mt, int& pos) {
    if (pos >= 624) {
        for (int i = 0; i < 624; i++) {
            unsigned int y = (mt[i] & 0x80000000u) | (mt[(i + 1) % 624] & 0x7fffffffu);
            unsigned int v = mt[(i + 397) % 624] ^ (y >> 1);
            if (y & 1u) v ^= 0x9908b0dfu;
            mt[i] = v;
        }
        pos = 0;
    }
    unsigned int y = mt[pos++];
    y ^= y >> 11;
    y ^= (y << 7) & 0x9d2c5680u;
    y ^= (y << 15) & 0xefc60000u;
    y ^= y >> 18;
    return y;
}

static constexpr unsigned int rk_interval(unsigned int mx, unsigned int* mt, int& pos) {
    if (mx == 0u) return 0u;
    unsigned int mask = mx;
    mask |= mask >> 1; mask |= mask >> 2; mask |= mask >> 4;
    mask |= mask >> 8; mask |= mask >> 16;
    while (true) {
        unsigned int value = mt_next(mt, pos) & mask;
        if (value <= mx) return value;
    }
}

static constexpr PermTable make_perms() {
    unsigned int mt[624] = {};
    unsigned int s = 0u;
    for (int i = 0; i < 624; i++) {
        mt[i] = s;
        s = 1812433253u * (s ^ (s >> 30)) + (unsigned int)i + 1u;
    }
    int pos = 624;
    PermTable t{};
    for (int k = 0; k < 3; k++) {
        int arr[NLEAF] = {};
        for (int i = 0; i < NLEAF; i++) arr[i] = i;
        for (int i = NLEAF - 1; i >= 1; i--) {
            unsigned int j = rk_interval((unsigned int)i, mt, pos);
            int tmp = arr[i]; arr[i] = arr[(int)j]; arr[(int)j] = tmp;
        }
        for (int i = 0; i < NLEAF; i++) t.p[k][i] = arr[i];
    }
    return t;
}

// ---------------------------------------------------------------------------
// Compile-time greedy leaf schedule minimizing simultaneously-open product
// groups across all 3 permutations, with slot allocation.
// ---------------------------------------------------------------------------
struct Sched {
    int leaf[NLEAF];
    int slot[NLEAF][3];
    unsigned char first[NLEAF];   // bit o: step opens perm-o's group
    unsigned char last[NLEAF];    // bit o: step closes perm-o's group
    int maxslots;
};

static constexpr Sched make_sched() {
    PermTable p = make_perms();
    int grp[3][NLEAF] = {};
    for (int o = 0; o < 3; o++)
        for (int i = 0; i < NLEAF; i++)
            grp[o][p.p[o][i]] = o * 32 + i / 4;

    int  cnt[96]   = {};
    int  gslot[96] = {};
    for (int g = 0; g < 96; g++) gslot[g] = -1;
    bool used[NLEAF] = {};
    bool slotfree[NLEAF] = {};
    for (int s2 = 0; s2 < NLEAF; s2++) slotfree[s2] = true;

    Sched sc{};
    int maxslot = 0;

    for (int step = 0; step < NLEAF; step++) {
        int best = -1, bestdelta = 99, besttie = -1;
        for (int j = 0; j < NLEAF; j++) {
            if (used[j]) continue;
            int delta = 0, tie = 0;
            for (int o = 0; o < 3; o++) {
                int g = grp[o][j];
                if (cnt[g] == 0) delta++;
                if (cnt[g] == 3) delta--;
                tie += cnt[g];
            }
            if (delta < bestdelta || (delta == bestdelta && tie > besttie)) {
                best = j; bestdelta = delta; besttie = tie;
            }
        }
        used[best] = true;
        sc.leaf[step] = best;
        sc.first[step] = 0; sc.last[step] = 0;
        for (int o = 0; o < 3; o++) {
            int g = grp[o][best];
            if (cnt[g] == 0) {
                int s2 = 0;
                while (!slotfree[s2]) s2++;
                slotfree[s2] = false;
                gslot[g] = s2;
                sc.first[step] = (unsigned char)(sc.first[step] | (1 << o));
                if (s2 + 1 > maxslot) maxslot = s2 + 1;
            }
            sc.slot[step][o] = gslot[g];
            cnt[g]++;
            if (cnt[g] == 4)
                sc.last[step] = (unsigned char)(sc.last[step] | (1 << o));
        }
        for (int o = 0; o < 3; o++) {
            int g = grp[o][best];
            if (cnt[g] == 4 && gslot[g] >= 0) {
                slotfree[gslot[g]] = true;
                gslot[g] = -1;
            }
        }
    }
    sc.maxslots = maxslot;
    return sc;
}

static constexpr Sched SCHED = make_sched();
static_assert(SCHED.maxslots <= POOL_SLOTS, "slot pool overflow");

// Materialized copy for runtime indexing in device code.
__device__ const Sched d_sched = make_sched();

// ---------------------------------------------------------------------------
// Device globals (STEP-indexed, i.e. already in schedule order)
//   g_m0 = {ctrl_bits, u1, u2, u3}
//          fermi: u1=aA, u2=aB, u3=Df(=dk?2B0:0)
//          bose : u1=DbC(=dk? C*(-2(lo1+1))*B0 : 0), u2=EfC(=dk?0:C), u3=PA(lo1>=1)
//   g_m1 = {B0*KF, B1, B2, B3}
//   g_off= {off0b | off1b<<16,  off2b | first<<16 | last<<19}  (byte offsets)
//   ctrl_bits: b0=fermi, b1=dk, b3=(lo1>=2)
// ---------------------------------------------------------------------------
__device__ float4 g_m0[NLEAF];
__device__ float4 g_m1[NLEAF];
__device__ uint2  g_off[NLEAF];
__device__ float  g_c [8];

__global__ void prep_kernel(const int* __restrict__ lftype,
                            const int* __restrict__ lforders,
                            const int* __restrict__ taui,
                            const int* __restrict__ tauo,
                            const int* __restrict__ momIdx,
                            const float* __restrict__ lb,
                            const float* __restrict__ lv0)
{
    int s = threadIdx.x;                  // step index
    const double PI_D   = 3.14159265358979323846264338327950288;
    const double LOG2E  = 1.44269504088896340735992468100189214;
    double KF_d = cbrt(9.0 * PI_D / 4.0) * 0.5;
    if (s == 0) {
        double EF   = KF_d * KF_d;
        double BETA = 10.0 / EF;
        double MAXK = 10.0 * KF_d;
        double t    = MAXK * 2.0 * PI_D * PI_D;
        double SC   = (t * t * t) * BETA * BETA / pow(2.0 * PI_D, 9.0);
        g_c[0] = (float)(BETA * LOG2E);     // BETA in log2 units
        g_c[1] = (float)(0.99177533 * EF);  // MU
        g_c[2] = (float)MAXK;
        g_c[3] = (float)SC;
        g_c[4] = (float)(PI_D / BETA);
    }
    int j   = d_sched.leaf[s];            // original leaf for this step
    int lt  = lftype[j];
    int lo1 = lforders[NLEAF + j];
    int dk  = (lforders[2 * NLEAF + j] == 1) ? 1 : 0;
    int ti  = taui[j];
    int to  = tauo[j];
    int m   = momIdx[j];

    bool fermi = (lt == 1);
    float B0  = lb[m];
    float B0K = (float)(KF_d) * B0;

    unsigned int bits = (fermi ? 1u : 0u)
                      | ((unsigned int)dk << 1)
                      | ((lo1 >= 2 ? 1u : 0u) << 3);

    float u1, u2, u3;
    if (fermi) {
        u1 = (float)((to == 1) - (ti == 1));            // aA
        u2 = (float)((to == 2) - (ti == 2));            // aB
        u3 = dk ? 2.0f * B0 : 0.0f;                     // Df
    } else {
        double C = 8.0 * PI_D * pow(0.5, (double)lo1);
        u1 = dk ? (float)(C * (-2.0 * (double)(lo1 + 1))) * B0 : 0.0f;  // DbC
        u2 = dk ? 0.0f : (float)C;                      // EfC
        u3 = (lo1 >= 1) ? 1.0f : 0.0f;                  // PA
    }

    unsigned int off0 = (unsigned int)d_sched.slot[s][0] * BT * 4;
    unsigned int off1 = (unsigned int)d_sched.slot[s][1] * BT * 4;
    unsigned int off2 = (unsigned int)d_sched.slot[s][2] * BT * 4;

    g_m0[s]  = make_float4(__uint_as_float(bits), u1, u2, u3);
    g_m1[s]  = make_float4(B0K, lb[NLEAF + m], lb[2 * NLEAF + m], lb[3 * NLEAF + m]);
    g_off[s] = make_uint2(off0 | (off1 << 16),
                          off2 | ((unsigned int)d_sched.first[s] << 16)
                               | ((unsigned int)d_sched.last[s]  << 19));
}

// ---------------------------------------------------------------------------
static __device__ __forceinline__ float ex2f(float x) {
    float r;
    asm("ex2.approx.ftz.f32 %0, %1;" : "=f"(r) : "f"(x));
    return r;
}
static __device__ __forceinline__ float rcpf(float x) {
    float r;
    asm("rcp.approx.ftz.f32 %0, %1;" : "=f"(r) : "f"(x));
    return r;
}

// ---------------------------------------------------------------------------
// Main kernel: 2 elements per thread, LOOPED over 128 steps (small I$ body),
// product-group pool in conflict-free shared memory (elem1 at +POOL_E1_OFF).
// ---------------------------------------------------------------------------
__global__ __launch_bounds__(BT, 7) void feyn_kernel(const float* __restrict__ var,
                                                     float* __restrict__ out,
                                                     int half)
{
    __shared__ float4 smA[NLEAF];
    __shared__ float4 smB[NLEAF];
    __shared__ uint2  smO[NLEAF];
    __shared__ float  pool[POOL_SLOTS * BT * 2];

    const int tid = threadIdx.x;
    #pragma unroll
    for (int j = tid; j < NLEAF; j += BT) {
        smA[j] = g_m0[j];
        smB[j] = g_m1[j];
        smO[j] = g_off[j];
    }
    __syncthreads();

    const int b0 = blockIdx.x * BT + tid;
    if (b0 >= half) return;
    const int b1 = b0 + half;          // second element (batch even)

    const float BETA2  = g_c[0];
    const float MUc    = g_c[1];
    const float MAXKc  = g_c[2];
    const float SCALEc = g_c[3];
    const float PHC    = g_c[4];

    // --- load both elements' variables ---
    float uxp[3], uyp[3], uzp[3], vxp[3], vyp[3], vzp[3];
    float facU, facV, ta0, ta1, tb0, tb1, va0U, va1U, va0V, va1V;
    {
        const float* p = var + (size_t)b0 * 11;
        va0U = __ldg(p + 0); va1U = __ldg(p + 1);
        ta0 = va0U * BETA2; tb0 = va1U * BETA2;
        facU = 1.0f;
        #pragma unroll
        for (int l = 0; l < 3; l++) {
            float pr = __ldg(p + 2 + l) * MAXKc;
            float th = __ldg(p + 5 + l) * 3.14159265358979f;
            float ph = __ldg(p + 8 + l) * 6.28318530717959f;
            float st, ct, sp, cp;
            __sincosf(th, &st, &ct);
            __sincosf(ph, &sp, &cp);
            float prst = pr * st;
            uxp[l] = prst * cp; uyp[l] = prst * sp; uzp[l] = pr * ct;
            facU *= pr * pr * st;
        }
    }
    {
        const float* p = var + (size_t)b1 * 11;
        va0V = __ldg(p + 0); va1V = __ldg(p + 1);
        ta1 = va0V * BETA2; tb1 = va1V * BETA2;
        facV = 1.0f;
        #pragma unroll
        for (int l = 0; l < 3; l++) {
            float pr = __ldg(p + 2 + l) * MAXKc;
            float th = __ldg(p + 5 + l) * 3.14159265358979f;
            float ph = __ldg(p + 8 + l) * 6.28318530717959f;
            float st, ct, sp, cp;
            __sincosf(th, &st, &ct);
            __sincosf(ph, &sp, &cp);
            float prst = pr * st;
            vxp[l] = prst * cp; vyp[l] = prst * sp; vzp[l] = pr * ct;
            facV *= pr * pr * st;
        }
    }

    char* Pbase = (char*)pool + tid * 4;   // this thread's column, elem0
    float a0 = 0.f, a1 = 0.f, a2 = 0.f;    // elem0 accumulators
    float c0 = 0.f, c1 = 0.f, c2 = 0.f;    // elem1 accumulators

    #pragma unroll 2
    for (int s = 0; s < NLEAF; s++) {
        const float4 m0 = smA[s];
        const float4 m1 = smB[s];
        const uint2  ow = smO[s];
        const unsigned int bits = __float_as_uint(m0.x);
        const float B1 = m1.y, B2 = m1.z, B3 = m1.w;

        // --- kq / k2 for both elements ---
        float kq0U = fmaf(uxp[0], B1, fmaf(uxp[1], B2, fmaf(uxp[2], B3, m1.x)));
        float kq1U = fmaf(uyp[0], B1, fmaf(uyp[1], B2, uyp[2] * B3));
        float kq2U = fmaf(uzp[0], B1, fmaf(uzp[1], B2, uzp[2] * B3));
        float k2U  = fmaf(kq0U, kq0U, fmaf(kq1U, kq1U, kq2U * kq2U));

        float kq0V = fmaf(vxp[0], B1, fmaf(vxp[1], B2, fmaf(vxp[2], B3, m1.x)));
        float kq1V = fmaf(vyp[0], B1, fmaf(vyp[1], B2, vyp[2] * B3));
        float kq2V = fmaf(vzp[0], B1, fmaf(vzp[1], B2, vzp[2] * B3));
        float k2V  = fmaf(kq0V, kq0V, fmaf(kq1V, kq1V, kq2V * kq2V));

        float valU, valV;
        if (bits & 1u) {
            // ---- fermi (uniform branch) ----
            float Ef = (bits & 2u) ? 0.0f : 1.0f;
            {
                float disp = k2U - MUc;
                float tau  = fmaf(m0.y, ta0, m0.z * tb0);
                bool  tp = tau  > 0.0f;
                float f1 = tp ? BETA2 : 0.0f;
                float f2 = (disp > 0.0f) ? -BETA2 : 0.0f;
                float ea  = ex2f(disp * ((f1 + f2) - tau));
                float den = 1.0f + ex2f(-fabsf(disp) * BETA2);
                float r   = rcpf(den);
                float mf  = fmaf(kq0U, m0.w, Ef);
                mf = tp ? mf : -mf;
                valU = (ea * r) * mf;
            }
            {
                float disp = k2V - MUc;
                float tau  = fmaf(m0.y, ta1, m0.z * tb1);
                bool  tp = tau  > 0.0f;
                float f1 = tp ? BETA2 : 0.0f;
                float f2 = (disp > 0.0f) ? -BETA2 : 0.0f;
                float ea  = ex2f(disp * ((f1 + f2) - tau));
                float den = 1.0f + ex2f(-fabsf(disp) * BETA2);
                float r   = rcpf(den);
                float mf  = fmaf(kq0V, m0.w, Ef);
                mf = tp ? mf : -mf;
                valV = (ea * r) * mf;
            }
        } else {
            // ---- bose ----
            float PB = (bits & 8u) ? 1.0f : 0.0f;
            {
                float r   = rcpf(k2U + 0.5f);
                float rm1 = r - 1.0f;
                float t1  = fmaf(m0.w, rm1, 1.0f);
                float t2  = fmaf(PB,   rm1, 1.0f);
                float mb  = fmaf(kq0U * r, m0.y, m0.z);
                valU = (r * t1) * (t2 * mb);
            }
            {
                float r   = rcpf(k2V + 0.5f);
                float rm1 = r - 1.0f;
                float t1  = fmaf(m0.w, rm1, 1.0f);
                float t2  = fmaf(PB,   rm1, 1.0f);
                float mb  = fmaf(kq0V * r, m0.y, m0.z);
                valV = (r * t1) * (t2 * mb);
            }
        }

        // --- product-group updates (pre-scaled byte offsets; elem1 at imm) ---
        const unsigned int fl = ow.y >> 16;   // first b0..2, last b3..5
        {
            float* q = (float*)(Pbase + (ow.x & 0xFFFFu));
            float n0 = (fl & 1u) ? valU : q[0] * valU;
            float n1 = (fl & 1u) ? valV : q[POOL_SLOTS * BT] * valV;
            q[0] = n0; q[POOL_SLOTS * BT] = n1;
            if (fl & 8u)  { a0 += n0; c0 += n1; }
        }
        {
            float* q = (float*)(Pbase + (ow.x >> 16));
            float n0 = (fl & 2u) ? valU : q[0] * valU;
            float n1 = (fl & 2u) ? valV : q[POOL_SLOTS * BT] * valV;
            q[0] = n0; q[POOL_SLOTS * BT] = n1;
            if (fl & 16u) { a1 += n0; c1 += n1; }
        }
        {
            float* q = (float*)(Pbase + (ow.y & 0xFFFFu));
            float n0 = (fl & 4u) ? valU : q[0] * valU;
            float n1 = (fl & 4u) ? valV : q[POOL_SLOTS * BT] * valV;
            q[0] = n0; q[POOL_SLOTS * BT] = n1;
            if (fl & 32u) { a2 += n0; c2 += n1; }
        }
    }

    {
        float ph1 = __cosf(PHC * va0U);
        float ph2 = __cosf(PHC * va1U);
        out[b0] = SCALEc * facU * (a0 + a1 * ph1 + a2 * ph2);
    }
    {
        float ph1 = __cosf(PHC * va0V);
        float ph2 = __cosf(PHC * va1V);
        out[b1] = SCALEc * facV * (c0 + c1 * ph1 + c2 * ph2);
    }
}

// ---------------------------------------------------------------------------
extern "C" void kernel_launch(void* const* d_in, const int* in_sizes, int n_in,
                              void* d_out, int out_size)
{
    const float* var      = (const float*)d_in[0];
    const int*   lftype   = (const int*)d_in[2];
    const int*   lforders = (const int*)d_in[3];
    const int*   taui     = (const int*)d_in[4];
    const int*   tauo     = (const int*)d_in[5];
    const int*   momIdx   = (const int*)d_in[6];
    const float* lb       = (const float*)d_in[7];
    const float* lv0      = (const float*)d_in[8];

    const int batch = in_sizes[0] / 11;
    const int half  = batch / 2;

    prep_kernel<<<1, NLEAF>>>(lftype, lforders, taui, tauo, momIdx, lb, lv0);

    const int grid = (half + BT - 1) / BT;
    feyn_kernel<<<grid, BT>>>(var, (float*)d_out, half);
}